// round 15
// baseline (speedup 1.0000x reference)
#include <cuda_runtime.h>
#include <math.h>

#define S_LEN 512
#define HID   256
#define NH    8
#define HD    32
#define SCALE_F 0.17677669529663687f   // 1/sqrt(32)
#define PI_F    3.14159265358979323846f
#define GK     256
#define NBLK   296u   // = 2 * 148 SMs: every SM holds exactly 2 blocks

// Scratch (no allocations allowed)
__device__ float g_qkv[3 * S_LEN * HID];
__device__ float g_ctx[S_LEN * HID];
__device__ unsigned g_bar[4];   // monotonic phase counters (replay-safe)

typedef unsigned long long ull;

__device__ __forceinline__ ull pack2(float lo, float hi) {
    ull r; asm("mov.b64 %0, {%1, %2};" : "=l"(r) : "f"(lo), "f"(hi)); return r;
}
__device__ __forceinline__ void unpack2(ull v, float& lo, float& hi) {
    asm("mov.b64 {%0, %1}, %2;" : "=f"(lo), "=f"(hi) : "l"(v));
}
#define FMA2(d, a, b, c) asm("fma.rn.f32x2 %0, %1, %2, %3;" : "=l"(d) : "l"(a), "l"(b), "l"(c))
#define MUL2(d, a, b)    asm("mul.rn.f32x2 %0, %1, %2;"     : "=l"(d) : "l"(a), "l"(b))
#define XOR64(d, a, b)   asm("xor.b64 %0, %1, %2;"          : "=l"(d) : "l"(a), "l"(b))

// Grid-wide barrier: monotonic counter, target = next multiple of NBLK.
// Works across CUDA-graph replays without reset. nanosleep keeps the spin
// from stealing issue slots from the co-resident working block.
__device__ __forceinline__ void grid_sync(int b) {
    __syncthreads();
    if (threadIdx.x == 0) {
        __threadfence();
        unsigned v = atomicAdd(&g_bar[b], 1u);
        unsigned target = v - (v % NBLK) + NBLK;
        volatile unsigned* p = &g_bar[b];
        while (*p < target) { __nanosleep(64); }
        __threadfence();
    }
    __syncthreads();
}

#define FUSED_SMEM (256 * 32 * 8 + 8 * 32 * 8)   // 67584 B (attn phase is max user)

__global__ void __launch_bounds__(256, 2)
fused_kernel(const float* __restrict__ x,
             const float* __restrict__ wq, const float* __restrict__ bq,
             const float* __restrict__ wk, const float* __restrict__ bk,
             const float* __restrict__ wv, const float* __restrict__ bv,
             const float* __restrict__ wo, const float* __restrict__ bo,
             float* __restrict__ out)
{
    extern __shared__ char sm[];
    const int tid = threadIdx.x;
    const int bid = blockIdx.x;

    // =====================================================================
    // Phase A: QKV projections. 96 jobs of 64m x 64n, full K=256 (<=148 SMs
    // -> at most ONE tile per SM). 256 threads, 4m x 4n = 16 outputs/thread.
    // Inner kk: 3x LDS.128 + 8x FMA2 (fma-bound).
    // =====================================================================
    if (bid < 96) {
        ull*   As2 = reinterpret_cast<ull*>(sm);                 // [32][66]
        float* Ws  = reinterpret_cast<float*>(sm + 32 * 66 * 8); // [32][68]

        const int z   = bid / 32;
        const int rem = bid & 31;
        const float* W  = (z == 0) ? wq : ((z == 1) ? wk : wv);
        const float* bi = (z == 0) ? bq : ((z == 1) ? bk : bv);
        float* C = g_qkv + z * (S_LEN * HID);
        const int m0 = (rem >> 2) * 64;      // 8 m-tiles
        const int n0 = (rem & 3) * 64;       // 4 n-tiles

        const int tm4 = (tid & 15) * 4;      // rows tm4..tm4+3
        const int tn4 = (tid >> 4) * 4;      // cols tn4..tn4+3
        const int sr  = tid >> 2;            // staging row 0..63
        const int sq  = tid & 3;             // staging k-group

        const float* Ap = x + (m0 + sr) * GK + 4 * sq;
        const float* Wp = W + (n0 + sr) * GK + 4 * sq;

        ull acc[4][2];
#pragma unroll
        for (int r = 0; r < 4; r++) { acc[r][0] = 0ull; acc[r][1] = 0ull; }

        float4 aA = *reinterpret_cast<const float4*>(Ap);
        float4 aB = *reinterpret_cast<const float4*>(Ap + 16);
        float4 wA = *reinterpret_cast<const float4*>(Wp);
        float4 wB = *reinterpret_cast<const float4*>(Wp + 16);

#pragma unroll 1
        for (int it = 0; it < 8; it++) {
            __syncthreads();
            As2[(4 * sq + 0) * 66 + sr] = pack2(aA.x, aA.x);
            As2[(4 * sq + 1) * 66 + sr] = pack2(aA.y, aA.y);
            As2[(4 * sq + 2) * 66 + sr] = pack2(aA.z, aA.z);
            As2[(4 * sq + 3) * 66 + sr] = pack2(aA.w, aA.w);
            As2[(16 + 4 * sq + 0) * 66 + sr] = pack2(aB.x, aB.x);
            As2[(16 + 4 * sq + 1) * 66 + sr] = pack2(aB.y, aB.y);
            As2[(16 + 4 * sq + 2) * 66 + sr] = pack2(aB.z, aB.z);
            As2[(16 + 4 * sq + 3) * 66 + sr] = pack2(aB.w, aB.w);
            Ws[(4 * sq + 0) * 68 + sr] = wA.x;
            Ws[(4 * sq + 1) * 68 + sr] = wA.y;
            Ws[(4 * sq + 2) * 68 + sr] = wA.z;
            Ws[(4 * sq + 3) * 68 + sr] = wA.w;
            Ws[(16 + 4 * sq + 0) * 68 + sr] = wB.x;
            Ws[(16 + 4 * sq + 1) * 68 + sr] = wB.y;
            Ws[(16 + 4 * sq + 2) * 68 + sr] = wB.z;
            Ws[(16 + 4 * sq + 3) * 68 + sr] = wB.w;
            __syncthreads();
            if (it < 7) {
                aA = *reinterpret_cast<const float4*>(Ap + (it + 1) * 32);
                aB = *reinterpret_cast<const float4*>(Ap + 16 + (it + 1) * 32);
                wA = *reinterpret_cast<const float4*>(Wp + (it + 1) * 32);
                wB = *reinterpret_cast<const float4*>(Wp + 16 + (it + 1) * 32);
            }
#pragma unroll
            for (int kk = 0; kk < 32; kk++) {
                ulonglong2 a01 = *reinterpret_cast<const ulonglong2*>(As2 + kk * 66 + tm4);
                ulonglong2 a23 = *reinterpret_cast<const ulonglong2*>(As2 + kk * 66 + tm4 + 2);
                ulonglong2 w   = *reinterpret_cast<const ulonglong2*>(Ws + kk * 68 + tn4);
                FMA2(acc[0][0], a01.x, w.x, acc[0][0]);
                FMA2(acc[0][1], a01.x, w.y, acc[0][1]);
                FMA2(acc[1][0], a01.y, w.x, acc[1][0]);
                FMA2(acc[1][1], a01.y, w.y, acc[1][1]);
                FMA2(acc[2][0], a23.x, w.x, acc[2][0]);
                FMA2(acc[2][1], a23.x, w.y, acc[2][1]);
                FMA2(acc[3][0], a23.y, w.x, acc[3][0]);
                FMA2(acc[3][1], a23.y, w.y, acc[3][1]);
            }
        }

        float4 b4 = *reinterpret_cast<const float4*>(bi + n0 + tn4);
#pragma unroll
        for (int r = 0; r < 4; r++) {
            float x0, x1, x2, x3;
            unpack2(acc[r][0], x0, x1); unpack2(acc[r][1], x2, x3);
            float4 o; o.x = x0 + b4.x; o.y = x1 + b4.y; o.z = x2 + b4.z; o.w = x3 + b4.w;
            *reinterpret_cast<float4*>(&C[(m0 + tm4 + r) * HID + n0 + tn4]) = o;
        }
    }
    grid_sync(0);

    // =====================================================================
    // Phase B: attention. 256 jobs = (32 i-tiles) x (8 heads), job = bid.
    // Each warp owns TWO i-rows sharing one V load.
    // =====================================================================
    if (bid < 256) {
        ull* Vs = reinterpret_cast<ull*>(sm);   // [256][32] j-pairs
        ull* Ps = Vs + 256 * 32;                // [8][32] partial V sums
        const int h  = bid & 7;
        const int ix = bid >> 3;
        const int d  = tid & 31;
        const int r  = tid >> 5;
        const int i0 = ix * 16 + 2 * r;
        const int i1 = i0 + 1;

        const float* gq = g_qkv;
        const float* gk = g_qkv + S_LEN * HID;
        const float* gv = g_qkv + 2 * S_LEN * HID;

        {
            float sve = 0.0f, svo = 0.0f;
#pragma unroll 4
            for (int kk = 0; kk < 32; kk++) {
                int k = r * 32 + kk;
                float v0 = gv[(2 * k)     * HID + h * HD + d];
                float v1 = gv[(2 * k + 1) * HID + h * HD + d];
                Vs[k * 32 + d] = pack2(v0, v1);
                sve += v0; svo += v1;
            }
            Ps[r * 32 + d] = pack2(sve, svo);
        }

        const int col = h * HD + d;

        ull X[2], NX[2], C2v[2], B2[2], acc[2];
        float sumw[2];
#pragma unroll
        for (int u = 0; u < 2; u++) {
            const int i = (u == 0) ? i0 : i1;
            const int idx = i * HID + col;
            const float qv = gq[idx];
            const float kv = gk[idx];
            const float vv = gv[idx];

            const float omega = PI_F / (1.0f + expf(-qv));   // sigmoid(q)*pi
            const float amp   = 1.0f / (1.0f + expf(-kv));   // sigmoid(k)
            const float phase = PI_F * tanhf(vv);            // tanh(v)*pi
            const float K0    = SCALE_F * amp;
            const float bmin  = 1.0f + K0 * K0 * 0.125f;     // minimax slope

            const float th0 = omega * (float)i + phase;
            float s0, c0, sw, cw;
            sincosf(th0, &s0, &c0);
            sincosf(omega, &sw, &cw);
            const float c2w = cw * cw - sw * sw;
            const float s2w = 2.0f * sw * cw;
            const float x0e = K0 * c0;
            const float x0o = K0 * (c0 * cw + s0 * sw);
            const float xme = K0 * (c0 * c2w - s0 * s2w);
            const float xmo = K0 * (c0 * cw - s0 * sw);

            // Denominator: sum_j (1 + b*x_j + x_j^2/2), closed-form Dirichlet
            const float sb2 = sinf(0.5f * omega);
            const float D1 = cosf(th0 - 255.5f * omega) * sinf(256.0f * omega) / sb2;
            const float D2 = cosf(2.0f * th0 - 511.0f * omega) * sinf(512.0f * omega) / sw;
            sumw[u] = 512.0f + bmin * K0 * D1
                    + 0.5f * K0 * K0 * (256.0f + 0.5f * D2);

            X[u]   = pack2(x0e, x0o);
            NX[u]  = pack2(-xme, -xmo);
            C2v[u] = pack2(2.0f * c2w, 2.0f * c2w);
            B2[u]  = pack2(bmin, bmin);
            acc[u] = 0ull;
        }

        const ull SMASK = 0x8000000080000000ULL;
        ull P2 = pack2(0.5f, 0.5f);

        __syncthreads();

        float svE = 0.0f, svO = 0.0f;
#pragma unroll
        for (int g = 0; g < 8; g++) {
            float pe, po;
            unpack2(Ps[g * 32 + d], pe, po);
            svE += pe; svO += po;
        }

        const ull* vp = Vs + d;

#pragma unroll 8
        for (int k = 0; k < 256; k++) {
            ull V2 = vp[k * 32];
#pragma unroll
            for (int u = 0; u < 2; u++) {
                ull rr, t2, Xn;
                FMA2(rr, X[u], P2, B2[u]);        // b + x/2
                MUL2(t2, X[u], V2);
                FMA2(acc[u], rr, t2, acc[u]);     // += x*(b+x/2)*V
                FMA2(Xn, C2v[u], X[u], NX[u]);    // Chebyshev step
                XOR64(NX[u], X[u], SMASK);
                X[u] = Xn;
            }
        }

        float ae, ao;
        unpack2(acc[0], ae, ao);
        g_ctx[i0 * HID + col] = (svE + svO + ae + ao) / sumw[0];
        unpack2(acc[1], ae, ao);
        g_ctx[i1 * HID + col] = (svE + svO + ae + ao) / sumw[1];
    }
    grid_sync(1);

    // =====================================================================
    // Phase C: out projection + bias, direct to out. 64 jobs of 64m x 32n,
    // full K=256. 4m x 2n per thread: 2x LDS.128 + 1x LDS.64 + 4x FMA2.
    // =====================================================================
    if (bid < 64) {
        ull*   As2 = reinterpret_cast<ull*>(sm);                 // [32][66]
        float* Ws  = reinterpret_cast<float*>(sm + 32 * 66 * 8); // [32][34]

        const int m0 = (bid >> 3) * 64;      // 8 m-tiles
        const int n0 = (bid & 7) * 32;       // 8 n-tiles

        const int tm4 = (tid & 15) * 4;      // rows tm4..+3
        const int tn2 = (tid >> 4) * 2;      // cols tn2..+1
        const int sr  = tid >> 2;            // A staging row 0..63
        const int sq  = tid & 3;
        const int wr  = tid >> 3;            // W staging row 0..31
        const int wq2 = tid & 7;

        const float* Ap = g_ctx + (m0 + sr) * GK + 4 * sq;
        const float* Wp = wo    + (n0 + wr) * GK + 4 * wq2;

        ull acc0 = 0ull, acc1 = 0ull, acc2 = 0ull, acc3 = 0ull;

        float4 aA = *reinterpret_cast<const float4*>(Ap);
        float4 aB = *reinterpret_cast<const float4*>(Ap + 16);
        float4 w4 = *reinterpret_cast<const float4*>(Wp);

#pragma unroll 1
        for (int it = 0; it < 8; it++) {
            __syncthreads();
            As2[(4 * sq + 0) * 66 + sr] = pack2(aA.x, aA.x);
            As2[(4 * sq + 1) * 66 + sr] = pack2(aA.y, aA.y);
            As2[(4 * sq + 2) * 66 + sr] = pack2(aA.z, aA.z);
            As2[(4 * sq + 3) * 66 + sr] = pack2(aA.w, aA.w);
            As2[(16 + 4 * sq + 0) * 66 + sr] = pack2(aB.x, aB.x);
            As2[(16 + 4 * sq + 1) * 66 + sr] = pack2(aB.y, aB.y);
            As2[(16 + 4 * sq + 2) * 66 + sr] = pack2(aB.z, aB.z);
            As2[(16 + 4 * sq + 3) * 66 + sr] = pack2(aB.w, aB.w);
            Ws[(4 * wq2 + 0) * 34 + wr] = w4.x;
            Ws[(4 * wq2 + 1) * 34 + wr] = w4.y;
            Ws[(4 * wq2 + 2) * 34 + wr] = w4.z;
            Ws[(4 * wq2 + 3) * 34 + wr] = w4.w;
            __syncthreads();
            if (it < 7) {
                aA = *reinterpret_cast<const float4*>(Ap + (it + 1) * 32);
                aB = *reinterpret_cast<const float4*>(Ap + 16 + (it + 1) * 32);
                w4 = *reinterpret_cast<const float4*>(Wp + (it + 1) * 32);
            }
#pragma unroll
            for (int kk = 0; kk < 32; kk++) {
                ulonglong2 a01 = *reinterpret_cast<const ulonglong2*>(As2 + kk * 66 + tm4);
                ulonglong2 a23 = *reinterpret_cast<const ulonglong2*>(As2 + kk * 66 + tm4 + 2);
                ull w01 = *reinterpret_cast<const ull*>(Ws + kk * 34 + tn2);
                FMA2(acc0, a01.x, w01, acc0);
                FMA2(acc1, a01.y, w01, acc1);
                FMA2(acc2, a23.x, w01, acc2);
                FMA2(acc3, a23.y, w01, acc3);
            }
        }

        const float b0 = bo[n0 + tn2];
        const float b1 = bo[n0 + tn2 + 1];
        float x0, x1;
        unpack2(acc0, x0, x1);
        *reinterpret_cast<float2*>(&out[(m0 + tm4 + 0) * HID + n0 + tn2]) = make_float2(x0 + b0, x1 + b1);
        unpack2(acc1, x0, x1);
        *reinterpret_cast<float2*>(&out[(m0 + tm4 + 1) * HID + n0 + tn2]) = make_float2(x0 + b0, x1 + b1);
        unpack2(acc2, x0, x1);
        *reinterpret_cast<float2*>(&out[(m0 + tm4 + 2) * HID + n0 + tn2]) = make_float2(x0 + b0, x1 + b1);
        unpack2(acc3, x0, x1);
        *reinterpret_cast<float2*>(&out[(m0 + tm4 + 3) * HID + n0 + tn2]) = make_float2(x0 + b0, x1 + b1);
    }
}

// ---------------------------------------------------------------------------
extern "C" void kernel_launch(void* const* d_in, const int* in_sizes, int n_in,
                              void* d_out, int out_size)
{
    const float* x  = (const float*)d_in[0];
    const float* wq = (const float*)d_in[1];
    const float* bq = (const float*)d_in[2];
    const float* wk = (const float*)d_in[3];
    const float* bk = (const float*)d_in[4];
    const float* wv = (const float*)d_in[5];
    const float* bv = (const float*)d_in[6];
    const float* wo = (const float*)d_in[7];
    const float* bo = (const float*)d_in[8];
    float* out = (float*)d_out;

    cudaFuncSetAttribute(fused_kernel, cudaFuncAttributeMaxDynamicSharedMemorySize, FUSED_SMEM);
    fused_kernel<<<NBLK, 256, FUSED_SMEM>>>(x, wq, bq, wk, bk, wv, bv, wo, bo, out);
}

// round 17
// speedup vs baseline: 1.4664x; 1.4664x over previous
#include <cuda_runtime.h>
#include <math.h>

#define S_LEN 512
#define HID   256
#define NH    8
#define HD    32
#define SCALE_F 0.17677669529663687f   // 1/sqrt(32)
#define PI_F    3.14159265358979323846f
#define GK     256

// Scratch (no allocations allowed)
__device__ float g_qkv[3 * S_LEN * HID];
__device__ float g_ctx[S_LEN * HID];

typedef unsigned long long ull;

__device__ __forceinline__ ull pack2(float lo, float hi) {
    ull r; asm("mov.b64 %0, {%1, %2};" : "=l"(r) : "f"(lo), "f"(hi)); return r;
}
__device__ __forceinline__ void unpack2(ull v, float& lo, float& hi) {
    asm("mov.b64 {%0, %1}, %2;" : "=f"(lo), "=f"(hi) : "l"(v));
}
#define FMA2(d, a, b, c) asm("fma.rn.f32x2 %0, %1, %2, %3;" : "=l"(d) : "l"(a), "l"(b), "l"(c))
#define MUL2(d, a, b)    asm("mul.rn.f32x2 %0, %1, %2;"     : "=l"(d) : "l"(a), "l"(b))
#define XOR64(d, a, b)   asm("xor.b64 %0, %1, %2;"          : "=l"(d) : "l"(a), "l"(b))

// ---------------------------------------------------------------------------
// GEMM with IN-BLOCK split-K=2.  C[m,n] = bias[n] + sum_c A[m,c]*W[n,c].
// 256 threads = two 128-thread groups; group g computes the K-half kb=g*128
// partial of the SAME 32x32 tile using the R7-proven body (2m x 4n per
// thread; inner kk = 2x LDS.64 bcast + 1x LDS.128 + 4x FMA2, conflict-free).
// Group 1 dumps partials to smem; group 0 reduces, adds bias, stores.
// Doubles warps/SM vs the 128-thread version at identical per-warp mix.
// ---------------------------------------------------------------------------
__device__ __forceinline__ void gemm_splitk_body(
    const float* __restrict__ A, const float* __restrict__ W,
    const float* __restrict__ bias, float* __restrict__ C)
{
    __shared__ ull   As2[2][32][33];   // [grp][k][m] (a,a) pairs
    __shared__ float Ws [2][32][36];   // [grp][k][n]

    const int t   = threadIdx.x & 127;
    const int grp = threadIdx.x >> 7;  // 0 or 1 -> K-half
    const int m0 = blockIdx.y * 32;
    const int n0 = blockIdx.x * 32;
    const int r  = t >> 3;             // 0..15
    const int c  = t & 7;              // 0..7
    const int kb = grp * 128;

    const float* Ap = A + (m0 + r) * GK + kb + 4 * c;
    const float* Wp = W + (n0 + r) * GK + kb + 4 * c;

    ull acc00 = 0ull, acc01 = 0ull, acc10 = 0ull, acc11 = 0ull;

    float4 a4a = *reinterpret_cast<const float4*>(Ap);
    float4 a4b = *reinterpret_cast<const float4*>(Ap + 16 * GK);
    float4 w4a = *reinterpret_cast<const float4*>(Wp);
    float4 w4b = *reinterpret_cast<const float4*>(Wp + 16 * GK);

#pragma unroll 1
    for (int it = 0; it < 4; it++) {
        __syncthreads();
        As2[grp][4*c + 0][r]      = pack2(a4a.x, a4a.x);
        As2[grp][4*c + 1][r]      = pack2(a4a.y, a4a.y);
        As2[grp][4*c + 2][r]      = pack2(a4a.z, a4a.z);
        As2[grp][4*c + 3][r]      = pack2(a4a.w, a4a.w);
        As2[grp][4*c + 0][16 + r] = pack2(a4b.x, a4b.x);
        As2[grp][4*c + 1][16 + r] = pack2(a4b.y, a4b.y);
        As2[grp][4*c + 2][16 + r] = pack2(a4b.z, a4b.z);
        As2[grp][4*c + 3][16 + r] = pack2(a4b.w, a4b.w);
        Ws[grp][4*c + 0][r]      = w4a.x; Ws[grp][4*c + 1][r]      = w4a.y;
        Ws[grp][4*c + 2][r]      = w4a.z; Ws[grp][4*c + 3][r]      = w4a.w;
        Ws[grp][4*c + 0][16 + r] = w4b.x; Ws[grp][4*c + 1][16 + r] = w4b.y;
        Ws[grp][4*c + 2][16 + r] = w4b.z; Ws[grp][4*c + 3][16 + r] = w4b.w;
        __syncthreads();
        if (it < 3) {
            a4a = *reinterpret_cast<const float4*>(Ap + (it + 1) * 32);
            a4b = *reinterpret_cast<const float4*>(Ap + 16 * GK + (it + 1) * 32);
            w4a = *reinterpret_cast<const float4*>(Wp + (it + 1) * 32);
            w4b = *reinterpret_cast<const float4*>(Wp + 16 * GK + (it + 1) * 32);
        }
#pragma unroll
        for (int kk = 0; kk < 32; kk++) {
            ull a0 = As2[grp][kk][2 * r];
            ull a1 = As2[grp][kk][2 * r + 1];
            const ull* wr = reinterpret_cast<const ull*>(&Ws[grp][kk][4 * c]);
            ull w01 = wr[0], w23 = wr[1];
            FMA2(acc00, a0, w01, acc00);
            FMA2(acc01, a0, w23, acc01);
            FMA2(acc10, a1, w01, acc10);
            FMA2(acc11, a1, w23, acc11);
        }
    }

    // Reduce the two K-half partials (reuse group-1 A staging as scratch).
    __syncthreads();
    ull* red = &As2[1][0][0];
    if (grp == 1) {
        red[t * 4 + 0] = acc00;
        red[t * 4 + 1] = acc01;
        red[t * 4 + 2] = acc10;
        red[t * 4 + 3] = acc11;
    }
    __syncthreads();
    if (grp == 0) {
        float4 b4 = *reinterpret_cast<const float4*>(bias + n0 + 4 * c);
        float x0, x1, x2, x3, y0, y1, y2, y3;
        unpack2(acc00, x0, x1); unpack2(acc01, x2, x3);
        unpack2(red[t * 4 + 0], y0, y1); unpack2(red[t * 4 + 1], y2, y3);
        {
            float4 o;
            o.x = x0 + y0 + b4.x; o.y = x1 + y1 + b4.y;
            o.z = x2 + y2 + b4.z; o.w = x3 + y3 + b4.w;
            *reinterpret_cast<float4*>(&C[(m0 + 2*r) * HID + n0 + 4*c]) = o;
        }
        unpack2(acc10, x0, x1); unpack2(acc11, x2, x3);
        unpack2(red[t * 4 + 2], y0, y1); unpack2(red[t * 4 + 3], y2, y3);
        {
            float4 o;
            o.x = x0 + y0 + b4.x; o.y = x1 + y1 + b4.y;
            o.z = x2 + y2 + b4.z; o.w = x3 + y3 + b4.w;
            *reinterpret_cast<float4*>(&C[(m0 + 2*r + 1) * HID + n0 + 4*c]) = o;
        }
    }
}

__global__ void __launch_bounds__(256)
gemm_qkv_kernel(const float* __restrict__ x,
                const float* __restrict__ wq, const float* __restrict__ bq,
                const float* __restrict__ wk, const float* __restrict__ bk,
                const float* __restrict__ wv, const float* __restrict__ bv)
{
    const int z = blockIdx.z;
    const float* W = (z == 0) ? wq : ((z == 1) ? wk : wv);
    const float* b = (z == 0) ? bq : ((z == 1) ? bk : bv);
    float* C = g_qkv + z * (S_LEN * HID);
    gemm_splitk_body(x, W, b, C);
}

__global__ void __launch_bounds__(256)
gemm_out_kernel(const float* __restrict__ wo, const float* __restrict__ bo,
                float* __restrict__ out)
{
    gemm_splitk_body(g_ctx, wo, bo, out);
}

// ---------------------------------------------------------------------------
// Attention (R14-passing version). Grid: (32 i-tiles, 8 heads), 256 threads =
// 8 warps x 32 d; each warp owns TWO i-rows sharing one V load.
// logit X_j = K0*cos(theta0 - j*omega), K0 = SCALE*sigmoid(k) <= 0.177.
// Weight p = 1 + b*X + X^2/2, minimax slope b = 1 + K0^2/8 (|err|<=K0^3/24).
// Numerator via Chebyshev recurrence (f32x2 even/odd j); sum V precomputed;
// denominator via closed-form Dirichlet sums D1, D2.
// ---------------------------------------------------------------------------
#define ATTN_SMEM (256 * 32 * 8 + 8 * 32 * 8)   // 67584 B

__global__ void __launch_bounds__(256)
attn_kernel()
{
    extern __shared__ ull Vs[];           // [256][32] j-pairs, then Ps[8][32]
    ull* Ps = Vs + 256 * 32;
    const int h   = blockIdx.y;
    const int tid = threadIdx.x;
    const int d   = tid & 31;
    const int r   = tid >> 5;             // warp id
    const int i0  = blockIdx.x * 16 + 2 * r;
    const int i1  = i0 + 1;

    const float* gq = g_qkv;
    const float* gk = g_qkv + S_LEN * HID;
    const float* gv = g_qkv + 2 * S_LEN * HID;

    // Stage V[h,:,:] as (even,odd) pairs + per-warp partial sums of V.
    {
        float sve = 0.0f, svo = 0.0f;
#pragma unroll 4
        for (int kk = 0; kk < 32; kk++) {
            int k = r * 32 + kk;
            float v0 = gv[(2 * k)     * HID + h * HD + d];
            float v1 = gv[(2 * k + 1) * HID + h * HD + d];
            Vs[k * 32 + d] = pack2(v0, v1);
            sve += v0; svo += v1;
        }
        Ps[r * 32 + d] = pack2(sve, svo);
    }

    const int col = h * HD + d;

    ull X[2], NX[2], C2v[2], B2[2], acc[2];
    float sumw[2];
#pragma unroll
    for (int u = 0; u < 2; u++) {
        const int i = (u == 0) ? i0 : i1;
        const int idx = i * HID + col;
        const float qv = gq[idx];
        const float kv = gk[idx];
        const float vv = gv[idx];

        const float omega = PI_F / (1.0f + expf(-qv));   // sigmoid(q)*pi
        const float amp   = 1.0f / (1.0f + expf(-kv));   // sigmoid(k)
        const float phase = PI_F * tanhf(vv);            // tanh(v)*pi
        const float K0    = SCALE_F * amp;
        const float bmin  = 1.0f + K0 * K0 * 0.125f;     // minimax slope

        const float th0 = omega * (float)i + phase;
        float s0, c0, sw, cw;
        sincosf(th0, &s0, &c0);
        sincosf(omega, &sw, &cw);
        const float c2w = cw * cw - sw * sw;
        const float s2w = 2.0f * sw * cw;
        const float x0e = K0 * c0;
        const float x0o = K0 * (c0 * cw + s0 * sw);
        const float xme = K0 * (c0 * c2w - s0 * s2w);
        const float xmo = K0 * (c0 * cw - s0 * sw);

        // Denominator: sum_j (1 + b*x_j + x_j^2/2), closed-form Dirichlet
        const float sb2 = sinf(0.5f * omega);
        const float D1 = cosf(th0 - 255.5f * omega) * sinf(256.0f * omega) / sb2;
        const float D2 = cosf(2.0f * th0 - 511.0f * omega) * sinf(512.0f * omega) / sw;
        sumw[u] = 512.0f + bmin * K0 * D1
                + 0.5f * K0 * K0 * (256.0f + 0.5f * D2);

        X[u]   = pack2(x0e, x0o);
        NX[u]  = pack2(-xme, -xmo);
        C2v[u] = pack2(2.0f * c2w, 2.0f * c2w);
        B2[u]  = pack2(bmin, bmin);
        acc[u] = 0ull;
    }

    const ull SMASK = 0x8000000080000000ULL;
    ull P2 = pack2(0.5f, 0.5f);

    __syncthreads();

    float svE = 0.0f, svO = 0.0f;
#pragma unroll
    for (int g = 0; g < 8; g++) {
        float pe, po;
        unpack2(Ps[g * 32 + d], pe, po);
        svE += pe; svO += po;
    }

    const ull* vp = Vs + d;

#pragma unroll 8
    for (int k = 0; k < 256; k++) {
        ull V2 = vp[k * 32];
#pragma unroll
        for (int u = 0; u < 2; u++) {
            ull rr, t2, Xn;
            FMA2(rr, X[u], P2, B2[u]);        // b + x/2
            MUL2(t2, X[u], V2);
            FMA2(acc[u], rr, t2, acc[u]);     // += x*(b+x/2)*V
            FMA2(Xn, C2v[u], X[u], NX[u]);    // Chebyshev step
            XOR64(NX[u], X[u], SMASK);
            X[u] = Xn;
        }
    }

    float ae, ao;
    unpack2(acc[0], ae, ao);
    g_ctx[i0 * HID + col] = (svE + svO + ae + ao) / sumw[0];
    unpack2(acc[1], ae, ao);
    g_ctx[i1 * HID + col] = (svE + svO + ae + ao) / sumw[1];
}

// ---------------------------------------------------------------------------
extern "C" void kernel_launch(void* const* d_in, const int* in_sizes, int n_in,
                              void* d_out, int out_size)
{
    const float* x  = (const float*)d_in[0];
    const float* wq = (const float*)d_in[1];
    const float* bq = (const float*)d_in[2];
    const float* wk = (const float*)d_in[3];
    const float* bk = (const float*)d_in[4];
    const float* wv = (const float*)d_in[5];
    const float* bv = (const float*)d_in[6];
    const float* wo = (const float*)d_in[7];
    const float* bo = (const float*)d_in[8];
    float* out = (float*)d_out;

    cudaFuncSetAttribute(attn_kernel, cudaFuncAttributeMaxDynamicSharedMemorySize, ATTN_SMEM);

    // QKV projections: (8 n) x (16 m) x 3 = 384 blocks of 256 threads
    gemm_qkv_kernel<<<dim3(HID / 32, S_LEN / 32, 3), 256>>>(x, wq, bq, wk, bk, wv, bv);

    // Attention: 32 i-tiles x 8 heads
    attn_kernel<<<dim3(S_LEN / 16, NH), 256, ATTN_SMEM>>>();

    // Output projection: 128 blocks of 256 threads
    gemm_out_kernel<<<dim3(HID / 32, S_LEN / 32), 256>>>(wo, bo, out);
}